// round 1
// baseline (speedup 1.0000x reference)
#include <cuda_runtime.h>
#include <math_constants.h>

// Problem constants
#define L_OBS   512
#define NSEG    8192
#define BPOSE   8
#define NRAY    (BPOSE * L_OBS)          // 4096
#define FOV_F   6.283185307179586
#define EPS_PAR 0.0001f

// Tiling
#define CHUNK   256                       // segments per chunk
#define NCHUNK  (NSEG / CHUNK)            // 32
#define TPB     256                       // threads per block (= rays per block)
#define RAYBLK  (NRAY / TPB)              // 16

// Scratch: per (chunk, ray) partial min-u. Every slot is written each launch.
__device__ float g_partial[NCHUNK * NRAY];

__global__ __launch_bounds__(TPB)
void raycast_partial_kernel(const float4* __restrict__ seg,
                            const float*  __restrict__ pose)
{
    __shared__ float4 s_pk[CHUNK];   // (sx, sy, dx, dy)
    __shared__ float  s_na[CHUNK];   // num_a

    const int tid  = threadIdx.x;
    const int ray  = blockIdx.y * TPB + tid;     // all rays in block share pose b
    const int b    = ray >> 9;                   // ray / 512
    const int beam = ray & (L_OBS - 1);

    const float px = pose[b * 3 + 0];
    const float py = pose[b * 3 + 1];
    const float th = pose[b * 3 + 2];

    // Cooperative precompute of per-(pose, segment) values for this chunk.
    {
        const int s = blockIdx.x * CHUNK + tid;
        float4 q = seg[s];                       // x3, y3, x4, y4
        float sx = q.z - q.x;
        float sy = q.w - q.y;
        float dx = px - q.x;                     // x1 - x3
        float dy = py - q.y;                     // y1 - y3
        s_pk[tid] = make_float4(sx, sy, dx, dy);
        s_na[tid] = sx * dy - sy * dx;           // num_a
    }
    __syncthreads();

    const float kstep = (float)(FOV_F / (double)L_OBS);
    const float bm  = (float)beam * kstep;
    const float ang = bm + th;
    const float rx = cosf(ang);
    const float ry = sinf(ang);

    // Track argmin of u = na/a over valid candidates WITHOUT dividing:
    // candidate (na, a) with na,a >= 0 beats best iff na*best_a < best_na*a.
    float best_na = CUDART_INF_F;
    float best_a  = 1.0f;

    #pragma unroll 4
    for (int i = 0; i < CHUNK; ++i) {
        float4 p = s_pk[i];                      // broadcast LDS.128
        float nai = s_na[i];                     // broadcast LDS.32
        float nb  = rx * p.w - ry * p.z;         // num_b
        float rxs = p.y * rx - p.x * ry;
        float a   = fabsf(rxs);
        // flip signs so that u_a = na/a, u_b = nbs/a with a = |rxs| > 0
        bool neg  = rxs < 0.0f;
        float na  = neg ? -nai : nai;
        float nbs = neg ? -nb  : nb;
        bool valid = (a >= EPS_PAR) & (na >= 0.0f) & (nbs >= 0.0f) & (nbs <= a);
        if (valid && (na * best_a < best_na * a)) {
            best_na = na;
            best_a  = a;
        }
    }

    // One full-precision division per (ray, chunk). |num_a|/|rxs| rounds
    // identically to num_a/rxs (division is sign-symmetric), matching ref.
    float u = best_na / best_a;                  // inf if no valid candidate
    g_partial[blockIdx.x * NRAY + ray] = u;
}

__global__ __launch_bounds__(TPB)
void raycast_finalize_kernel(const float4* __restrict__ seg,
                             const float*  __restrict__ pose,
                             float*        __restrict__ out)
{
    const int ray  = blockIdx.x * TPB + threadIdx.x;
    const int b    = ray >> 9;
    const int beam = ray & (L_OBS - 1);

    float best = CUDART_INF_F;
    #pragma unroll
    for (int c = 0; c < NCHUNK; ++c) {
        float v = g_partial[c * NRAY + ray];
        best = fminf(best, v);
    }

    const float px = pose[b * 3 + 0];
    const float py = pose[b * 3 + 1];
    const float th = pose[b * 3 + 2];

    const float kstep = (float)(FOV_F / (double)L_OBS);
    const float bm  = (float)beam * kstep;
    const float ang = bm + th;
    const float rx = cosf(ang);
    const float ry = sinf(ang);

    float u = best;
    if (isinf(best)) {
        // Reference: argmin over all-inf returns idx 0 -> u_sel = u_a[0]
        // (with parallel -> 0.0 substitution).
        float4 q = seg[0];
        float sx = q.z - q.x;
        float sy = q.w - q.y;
        float dx = px - q.x;
        float dy = py - q.y;
        float num_a = sx * dy - sy * dx;
        float rxs   = sy * rx - sx * ry;
        u = (fabsf(rxs) < EPS_PAR) ? 0.0f : (num_a / rxs);
    }

    const float ix = px + rx * u;
    const float iy = py + ry * u;

    // obs_global: [B, L_OBS, 2] at out[0 .. 8192)
    const int gi = (b * L_OBS + beam) * 2;
    out[gi + 0] = ix;
    out[gi + 1] = iy;

    // obs_local = (obs_global - c0) @ R,  R = [[c,-s],[s,c]]
    const float c = cosf(th);
    const float s = sinf(th);
    const float ddx = ix - px;
    const float ddy = iy - py;
    out[NRAY * 2 + gi + 0] =  ddx * c + ddy * s;
    out[NRAY * 2 + gi + 1] = -ddx * s + ddy * c;
}

extern "C" void kernel_launch(void* const* d_in, const int* in_sizes, int n_in,
                              void* d_out, int out_size)
{
    const float4* seg  = (const float4*)d_in[0];   // line_seg [8192, 4]
    const float*  pose = (const float*)d_in[1];    // pose [8, 3]
    float* out = (float*)d_out;                    // [2 * 8 * 512 * 2] floats

    dim3 grid1(NCHUNK, RAYBLK);
    raycast_partial_kernel<<<grid1, TPB>>>(seg, pose);
    raycast_finalize_kernel<<<RAYBLK, TPB>>>(seg, pose, out);
}